// round 12
// baseline (speedup 1.0000x reference)
#include <cuda_runtime.h>
#include <cuda_bf16.h>
#include <cstdint>

#define D 64
#define MTILE 128
#define THREADS 256
#define N_NODES_MAX 50000

__device__ float g_aggr[N_NODES_MAX * D];   // S = segment_sum(h)
__device__ float g_deg[N_NODES_MAX];
__device__ float g_P[N_NODES_MAX * D];      // x @ W1_top
__device__ float g_Q[N_NODES_MAX * D];      // x @ W1_bot
__device__ float g_R[N_NODES_MAX * D];      // x @ U1_top
__device__ float g_W2U1b[D * D];            // W2 @ U1_bot
__device__ float g_v[D];                    // b2 @ U1_bot

// ---------- precompute kernel smem ----------
#define PR_X_HI   0
#define PR_X_LO   16384
#define PR_W1T_HI 32768
#define PR_W1T_LO 40960
#define PR_W1B_HI 49152
#define PR_W1B_LO 57344
#define PR_U1T_HI 65536
#define PR_U1T_LO 73728
#define PR_SMEM   81920
// ---------- node kernel smem (H overlays A) ----------
#define ND_A_HI 0
#define ND_A_LO 16384
#define ND_WF_HI 32768
#define ND_WF_LO 40960
#define ND_U2_HI 49152
#define ND_U2_LO 57344
#define ND_B1 65536
#define ND_B2 65792
#define ND_V  66048
#define ND_SMEM 66304

static __device__ __forceinline__ uint32_t smem_u32(const void* p) {
    uint32_t a;
    asm("{ .reg .u64 t; cvta.to.shared.u64 t, %1; cvt.u32.u64 %0, t; }" : "=r"(a) : "l"(p));
    return a;
}
static __device__ __forceinline__ uint32_t swz(uint32_t off) {
    return off ^ ((off >> 3) & 0x70);
}
static __device__ __forceinline__ void ldsm_x4(uint32_t* r, uint32_t addr) {
    asm volatile("ldmatrix.sync.aligned.m8n8.x4.shared.b16 {%0,%1,%2,%3}, [%4];"
                 : "=r"(r[0]), "=r"(r[1]), "=r"(r[2]), "=r"(r[3]) : "r"(addr));
}
static __device__ __forceinline__ void mma_bf16(float* c, const uint32_t* a, const uint32_t* b) {
    asm volatile("mma.sync.aligned.m16n8k16.row.col.f32.bf16.bf16.f32 "
                 "{%0,%1,%2,%3}, {%4,%5,%6,%7}, {%8,%9}, {%0,%1,%2,%3};"
                 : "+f"(c[0]), "+f"(c[1]), "+f"(c[2]), "+f"(c[3])
                 : "r"(a[0]), "r"(a[1]), "r"(a[2]), "r"(a[3]), "r"(b[0]), "r"(b[1]));
}
static __device__ __forceinline__ void split2(float a, float b, uint32_t& hi, uint32_t& lo) {
    __nv_bfloat162 h = __floats2bfloat162_rn(a, b);
    float ra = a - __bfloat162float(h.x);
    float rb = b - __bfloat162float(h.y);
    __nv_bfloat162 l = __floats2bfloat162_rn(ra, rb);
    hi = *(uint32_t*)&h; lo = *(uint32_t*)&l;
}
static __device__ __forceinline__ void red_add_v4(float* p, float a, float b, float c, float d) {
    asm volatile("red.global.add.v4.f32 [%0], {%1,%2,%3,%4};"
                 :: "l"(p), "f"(a), "f"(b), "f"(c), "f"(d) : "memory");
}
static __device__ __forceinline__ void red_add_f32(float* p, float a) {
    asm volatile("red.global.add.f32 [%0], %1;" :: "l"(p), "f"(a) : "memory");
}

// W row-major [K][64] f32 -> bf16 hi/lo tiles [n][k], 128B SW128 rows
static __device__ __forceinline__ void load_w_tiles(char* smem, const float* W, int K,
                                                    int off_hi0, int off_lo0, int off_hi1, int off_lo1) {
    for (int i = threadIdx.x; i < K * 64; i += THREADS) {
        int k = i >> 6, n = i & 63;
        float v = W[i];
        __nv_bfloat16 h = __float2bfloat16(v);
        float r = v - __bfloat162float(h);
        __nv_bfloat16 l = __float2bfloat16(r);
        int half = k >> 6; int kk = k & 63;
        uint32_t so = swz((uint32_t)(n * 128 + kk * 2));
        *(__nv_bfloat16*)(smem + (half ? off_hi1 : off_hi0) + so) = h;
        *(__nv_bfloat16*)(smem + (half ? off_lo1 : off_lo0) + so) = l;
    }
}

// 3-term hi/lo GEMM: acc += Ahi*Bhi + Alo*Bhi + Ahi*Blo, [128x64]@[64x64]
static __device__ __forceinline__ void gemm_hl(uint32_t sb, uint32_t aHi, uint32_t aLo,
                                               uint32_t bHi, uint32_t bLo,
                                               int wm, int wn, int lane, float acc[2][4][4]) {
    const int arow = lane & 15, acolb = (lane >> 4) * 16;
    const int brow = (lane & 7) + ((lane & 16) ? 8 : 0), bcolb = ((lane >> 3) & 1) * 16;
    #pragma unroll
    for (int s = 0; s < 2; ++s)
        #pragma unroll
        for (int t4 = 0; t4 < 4; ++t4)
            #pragma unroll
            for (int o = 0; o < 4; ++o) acc[s][t4][o] = 0.0f;
    #pragma unroll
    for (int k = 0; k < 4; ++k) {
        uint32_t a[2][2][4], b[2][2][4];
        #pragma unroll
        for (int s = 0; s < 2; ++s) {
            ldsm_x4(a[0][s], sb + aHi + swz((uint32_t)((wm * 32 + s * 16 + arow) * 128 + k * 32 + acolb)));
            ldsm_x4(a[1][s], sb + aLo + swz((uint32_t)((wm * 32 + s * 16 + arow) * 128 + k * 32 + acolb)));
        }
        #pragma unroll
        for (int t = 0; t < 2; ++t) {
            ldsm_x4(b[0][t], sb + bHi + swz((uint32_t)((wn * 32 + t * 16 + brow) * 128 + k * 32 + bcolb)));
            ldsm_x4(b[1][t], sb + bLo + swz((uint32_t)((wn * 32 + t * 16 + brow) * 128 + k * 32 + bcolb)));
        }
        #pragma unroll
        for (int s = 0; s < 2; ++s)
            #pragma unroll
            for (int t4 = 0; t4 < 4; ++t4) {
                mma_bf16(acc[s][t4], a[0][s], &b[0][t4 >> 1][(t4 & 1) * 2]);
                mma_bf16(acc[s][t4], a[1][s], &b[0][t4 >> 1][(t4 & 1) * 2]);
                mma_bf16(acc[s][t4], a[0][s], &b[1][t4 >> 1][(t4 & 1) * 2]);
            }
    }
}

// ---------------- wprep: W2U1b = W2 @ U1_bot, v = b2 @ U1_bot (one block) ----------------
__global__ void __launch_bounds__(THREADS)
wprep_kernel(const float* __restrict__ W2, const float* __restrict__ U1,
             const float* __restrict__ b2)
{
    const float* U1b = U1 + 64 * D;
    const int tid = threadIdx.x;
    // 4096 outputs, 16 per thread
    for (int o = tid; o < D * D; o += THREADS) {
        int k = o >> 6, n = o & 63;
        float s = 0.0f;
        #pragma unroll 8
        for (int j = 0; j < D; ++j)
            s += W2[k * D + j] * U1b[j * D + n];
        g_W2U1b[o] = s;
    }
    if (tid < D) {
        float s = 0.0f;
        #pragma unroll 8
        for (int j = 0; j < D; ++j)
            s += b2[j] * U1b[j * D + tid];
        g_v[tid] = s;
    }
}

// ---------------- precompute: P = x@W1t, Q = x@W1b, R = x@U1t ----------------
__global__ void __launch_bounds__(THREADS)
precompute_kernel(const float* __restrict__ x,
                  const float* __restrict__ W1, const float* __restrict__ U1,
                  int nNodes)
{
    extern __shared__ char smem[];
    const uint32_t sb = smem_u32(smem);
    const int tid = threadIdx.x;
    const int lane = tid & 31, w = tid >> 5;
    const int wm = w >> 1, wn = w & 1;
    const int rA = wm * 32 + (lane >> 2);
    const int cA = wn * 32 + (lane & 3) * 2;

    load_w_tiles(smem, W1, 128, PR_W1T_HI, PR_W1T_LO, PR_W1B_HI, PR_W1B_LO);
    load_w_tiles(smem, U1, 64,  PR_U1T_HI, PR_U1T_LO, PR_U1T_HI, PR_U1T_LO);

    const int nTiles = (nNodes + MTILE - 1) / MTILE;
    for (int t = blockIdx.x; t < nTiles; t += gridDim.x) {
        const int n0 = t * MTILE;
        __syncthreads();
        #pragma unroll 4
        for (int it = 0; it < 8; ++it) {
            int idx = tid + it * THREADS;
            int q = idx & 15;
            int e = idx >> 4;
            int nd = n0 + e; if (nd >= nNodes) nd = nNodes - 1;
            float4 v = ((const float4*)x)[nd * 16 + q];
            uint32_t h01, l01, h23, l23;
            split2(v.x, v.y, h01, l01);
            split2(v.z, v.w, h23, l23);
            uint32_t so = swz((uint32_t)(e * 128 + q * 8));
            *(uint2*)(smem + PR_X_HI + so) = make_uint2(h01, h23);
            *(uint2*)(smem + PR_X_LO + so) = make_uint2(l01, l23);
        }
        __syncthreads();

        float acc[2][4][4];
        #define PR_STORE(OARR) do { \
            _Pragma("unroll") for (int s = 0; s < 2; ++s) \
            _Pragma("unroll") for (int t4 = 0; t4 < 4; ++t4) { \
                int col = cA + t4 * 8, row = rA + s * 16, n1 = n0 + row; \
                if (n1 < nNodes) *(float2*)&OARR[n1 * D + col] = make_float2(acc[s][t4][0], acc[s][t4][1]); \
                if (n1 + 8 < nNodes) *(float2*)&OARR[(n1 + 8) * D + col] = make_float2(acc[s][t4][2], acc[s][t4][3]); \
            } } while (0)

        gemm_hl(sb, PR_X_HI, PR_X_LO, PR_W1T_HI, PR_W1T_LO, wm, wn, lane, acc);
        PR_STORE(g_P);
        gemm_hl(sb, PR_X_HI, PR_X_LO, PR_W1B_HI, PR_W1B_LO, wm, wn, lane, acc);
        PR_STORE(g_Q);
        gemm_hl(sb, PR_X_HI, PR_X_LO, PR_U1T_HI, PR_U1T_LO, wm, wn, lane, acc);
        PR_STORE(g_R);
        #undef PR_STORE
    }
}

// ---------------- edge kernel (streaming): red(relu(P[dst]+Q[src]+b1) -> S[dst]), deg++ ----------------
__global__ void __launch_bounds__(THREADS)
edge_kernel(const void* __restrict__ ei,
            const float* __restrict__ b1,
            int nEdges, int nNodes)
{
    const int tid = threadIdx.x;
    // per-block is64 detection (int64 data => odd 32-bit words are 0)
    const int* ei32 = (const int*)ei;
    int nz = 0;
    if (tid < 64) nz = (ei32[2 * tid + 1] != 0);
    const int is64 = !__syncthreads_or(nz);
    const long long* ei64 = (const long long*)ei;

    const int q = tid & 15;
    const float4 b1q = ((const float4*)b1)[q];
    const int egrp0 = (blockIdx.x * THREADS + tid) >> 4;
    const int estride = (gridDim.x * THREADS) >> 4;

    for (int e = egrp0; e < nEdges; e += estride) {
        int sn = is64 ? (int)ei64[e] : ei32[e];
        int dn = is64 ? (int)ei64[nEdges + e] : ei32[nEdges + e];
        sn = min(max(sn, 0), nNodes - 1);
        dn = min(max(dn, 0), nNodes - 1);
        float4 p = ((const float4*)g_P)[dn * 16 + q];
        float4 qq = ((const float4*)g_Q)[sn * 16 + q];
        float v0 = fmaxf(p.x + qq.x + b1q.x, 0.0f);
        float v1 = fmaxf(p.y + qq.y + b1q.y, 0.0f);
        float v2 = fmaxf(p.z + qq.z + b1q.z, 0.0f);
        float v3 = fmaxf(p.w + qq.w + b1q.w, 0.0f);
        red_add_v4(&g_aggr[dn * D + q * 4], v0, v1, v2, v3);
        if (q == 0) red_add_f32(&g_deg[dn], 1.0f);
    }
}

// ---------------- node kernel: out = relu(R + S@W2U1b + deg*v + ub1)@U2 + ub2 ----------------
__global__ void __launch_bounds__(THREADS, 2)
node_kernel(const float* __restrict__ ub1, const float* __restrict__ ub2,
            const float* __restrict__ U2,
            float* __restrict__ out, int nNodes)
{
    extern __shared__ char smem[];
    const uint32_t sb = smem_u32(smem);
    const int tid = threadIdx.x;
    const int lane = tid & 31, w = tid >> 5;
    const int wm = w >> 1, wn = w & 1;
    const int rA = wm * 32 + (lane >> 2);
    const int cA = wn * 32 + (lane & 3) * 2;
    float* sB1 = (float*)(smem + ND_B1);
    float* sB2 = (float*)(smem + ND_B2);
    float* sV  = (float*)(smem + ND_V);

    load_w_tiles(smem, g_W2U1b, 64, ND_WF_HI, ND_WF_LO, ND_WF_HI, ND_WF_LO);
    load_w_tiles(smem, U2, 64, ND_U2_HI, ND_U2_LO, ND_U2_HI, ND_U2_LO);
    if (tid < 64) { sB1[tid] = ub1[tid]; sB2[tid] = ub2[tid]; sV[tid] = g_v[tid]; }

    const int nTiles = (nNodes + MTILE - 1) / MTILE;
    for (int t = blockIdx.x; t < nTiles; t += gridDim.x) {
        const int n0 = t * MTILE;
        __syncthreads();

        // gather S -> A hi/lo (coalesced)
        #pragma unroll 4
        for (int it = 0; it < 8; ++it) {
            int idx = tid + it * THREADS;
            int q = idx & 15;
            int e = idx >> 4;
            int nd = n0 + e; if (nd >= nNodes) nd = nNodes - 1;
            float4 v = ((const float4*)g_aggr)[nd * 16 + q];
            uint32_t h01, l01, h23, l23;
            split2(v.x, v.y, h01, l01);
            split2(v.z, v.w, h23, l23);
            uint32_t so = swz((uint32_t)(e * 128 + q * 8));
            *(uint2*)(smem + ND_A_HI + so) = make_uint2(h01, h23);
            *(uint2*)(smem + ND_A_LO + so) = make_uint2(l01, l23);
        }
        __syncthreads();

        float acc[2][4][4];
        gemm_hl(sb, ND_A_HI, ND_A_LO, ND_WF_HI, ND_WF_LO, wm, wn, lane, acc);
        __syncthreads();   // all warps done reading A before overlay write

        // h = relu(acc + R + deg*v + ub1) -> H (overlays A)
        #pragma unroll
        for (int s = 0; s < 2; ++s) {
            int row = rA + s * 16;
            int n1 = n0 + row;
            float dg0 = (n1 < nNodes) ? g_deg[n1] : 0.0f;
            float dg1 = (n1 + 8 < nNodes) ? g_deg[n1 + 8] : 0.0f;
            #pragma unroll
            for (int t4 = 0; t4 < 4; ++t4) {
                int col = cA + t4 * 8;
                float2 ra = (n1 < nNodes) ? *(const float2*)&g_R[n1 * D + col] : make_float2(0.f, 0.f);
                float2 rb = (n1 + 8 < nNodes) ? *(const float2*)&g_R[(n1 + 8) * D + col] : make_float2(0.f, 0.f);
                float v0 = fmaxf(acc[s][t4][0] + ra.x + dg0 * sV[col]     + sB1[col],     0.0f);
                float v1 = fmaxf(acc[s][t4][1] + ra.y + dg0 * sV[col + 1] + sB1[col + 1], 0.0f);
                uint32_t hi, lo; split2(v0, v1, hi, lo);
                uint32_t so = swz((uint32_t)(row * 128 + col * 2));
                *(uint32_t*)(smem + ND_A_HI + so) = hi;
                *(uint32_t*)(smem + ND_A_LO + so) = lo;
                float v2 = fmaxf(acc[s][t4][2] + rb.x + dg1 * sV[col]     + sB1[col],     0.0f);
                float v3 = fmaxf(acc[s][t4][3] + rb.y + dg1 * sV[col + 1] + sB1[col + 1], 0.0f);
                split2(v2, v3, hi, lo);
                so = swz((uint32_t)((row + 8) * 128 + col * 2));
                *(uint32_t*)(smem + ND_A_HI + so) = hi;
                *(uint32_t*)(smem + ND_A_LO + so) = lo;
            }
        }
        __syncthreads();

        float acc2[2][4][4];
        gemm_hl(sb, ND_A_HI, ND_A_LO, ND_U2_HI, ND_U2_LO, wm, wn, lane, acc2);

        #pragma unroll
        for (int s = 0; s < 2; ++s)
            #pragma unroll
            for (int t4 = 0; t4 < 4; ++t4) {
                int col = cA + t4 * 8;
                int row = rA + s * 16;
                int n1 = n0 + row;
                if (n1 < nNodes)
                    *(float2*)&out[n1 * D + col] =
                        make_float2(acc2[s][t4][0] + sB2[col], acc2[s][t4][1] + sB2[col + 1]);
                if (n1 + 8 < nNodes)
                    *(float2*)&out[(n1 + 8) * D + col] =
                        make_float2(acc2[s][t4][2] + sB2[col], acc2[s][t4][3] + sB2[col + 1]);
            }
    }
}

extern "C" void kernel_launch(void* const* d_in, const int* in_sizes, int n_in,
                              void* d_out, int out_size)
{
    const float* x   = (const float*)d_in[0];
    const void*  ei  = d_in[1];
    const float* W1  = (const float*)d_in[2];
    const float* b1  = (const float*)d_in[3];
    const float* W2  = (const float*)d_in[4];
    const float* b2  = (const float*)d_in[5];
    const float* U1  = (const float*)d_in[6];
    const float* ub1 = (const float*)d_in[7];
    const float* U2  = (const float*)d_in[8];
    const float* ub2 = (const float*)d_in[9];
    float* out = (float*)d_out;

    const int nEdges = in_sizes[1] / 2;
    const int nNodes = in_sizes[0] / D;

    void* aggr_ptr = nullptr;
    void* deg_ptr = nullptr;
    cudaGetSymbolAddress(&aggr_ptr, g_aggr);
    cudaGetSymbolAddress(&deg_ptr, g_deg);

    cudaFuncSetAttribute(precompute_kernel, cudaFuncAttributeMaxDynamicSharedMemorySize, PR_SMEM);
    cudaFuncSetAttribute(node_kernel, cudaFuncAttributeMaxDynamicSharedMemorySize, ND_SMEM);

    const int nodeTiles = (nNodes + MTILE - 1) / MTILE;

    // edge_kernel is the 5th launch (ncu profiles launch #5)
    cudaMemsetAsync(aggr_ptr, 0, (size_t)nNodes * D * sizeof(float), 0);        // 1
    cudaMemsetAsync(deg_ptr, 0, (size_t)nNodes * sizeof(float), 0);             // 2
    wprep_kernel<<<1, THREADS>>>(W2, U1, b2);                                   // 3
    precompute_kernel<<<nodeTiles < 148 ? nodeTiles : 148, THREADS, PR_SMEM>>>(  // 4
        x, W1, U1, nNodes);
    edge_kernel<<<1776, THREADS>>>(ei, b1, nEdges, nNodes);                     // 5
    node_kernel<<<nodeTiles < 296 ? nodeTiles : 296, THREADS, ND_SMEM>>>(       // 6
        ub1, ub2, U2, out, nNodes);
}

// round 13
// speedup vs baseline: 1.5844x; 1.5844x over previous
#include <cuda_runtime.h>
#include <cuda_bf16.h>
#include <cstdint>

#define D 64
#define MTILE 128
#define THREADS 256
#define N_NODES_MAX 50000
#define N_EDGES_MAX 1000000
#define NCHUNK ((N_NODES_MAX + 255) / 256)   // 196

__device__ float g_aggr[N_NODES_MAX * D];   // S = segment_sum(relu(P[dst]+Q[src]+b1))
__device__ float g_P[N_NODES_MAX * D];      // x @ W1_top
__device__ float g_Q[N_NODES_MAX * D];      // x @ W1_bot
__device__ float g_R[N_NODES_MAX * D];      // x @ U1_top
__device__ float g_W2U1b[D * D];            // W2 @ U1_bot
__device__ float g_v[D];                    // b2 @ U1_bot
__device__ int g_cnt[N_NODES_MAX];          // per-dst degree (histogram)
__device__ int g_start[N_NODES_MAX];        // exclusive prefix of cnt
__device__ int g_cur[N_NODES_MAX];          // fill cursors
__device__ int g_btot[256];
__device__ int g_boff[256];
__device__ int g_elist[N_EDGES_MAX];        // src ids binned by dst

// ---------- precompute kernel smem ----------
#define PR_X_HI   0
#define PR_X_LO   16384
#define PR_W1T_HI 32768
#define PR_W1T_LO 40960
#define PR_W1B_HI 49152
#define PR_W1B_LO 57344
#define PR_U1T_HI 65536
#define PR_U1T_LO 73728
#define PR_SMEM   81920
// ---------- node kernel smem (H overlays A) ----------
#define ND_A_HI 0
#define ND_A_LO 16384
#define ND_WF_HI 32768
#define ND_WF_LO 40960
#define ND_U2_HI 49152
#define ND_U2_LO 57344
#define ND_B1 65536
#define ND_B2 65792
#define ND_V  66048
#define ND_SMEM 66304

static __device__ __forceinline__ uint32_t smem_u32(const void* p) {
    uint32_t a;
    asm("{ .reg .u64 t; cvta.to.shared.u64 t, %1; cvt.u32.u64 %0, t; }" : "=r"(a) : "l"(p));
    return a;
}
static __device__ __forceinline__ uint32_t swz(uint32_t off) {
    return off ^ ((off >> 3) & 0x70);
}
static __device__ __forceinline__ void ldsm_x4(uint32_t* r, uint32_t addr) {
    asm volatile("ldmatrix.sync.aligned.m8n8.x4.shared.b16 {%0,%1,%2,%3}, [%4];"
                 : "=r"(r[0]), "=r"(r[1]), "=r"(r[2]), "=r"(r[3]) : "r"(addr));
}
static __device__ __forceinline__ void mma_bf16(float* c, const uint32_t* a, const uint32_t* b) {
    asm volatile("mma.sync.aligned.m16n8k16.row.col.f32.bf16.bf16.f32 "
                 "{%0,%1,%2,%3}, {%4,%5,%6,%7}, {%8,%9}, {%0,%1,%2,%3};"
                 : "+f"(c[0]), "+f"(c[1]), "+f"(c[2]), "+f"(c[3])
                 : "r"(a[0]), "r"(a[1]), "r"(a[2]), "r"(a[3]), "r"(b[0]), "r"(b[1]));
}
static __device__ __forceinline__ void split2(float a, float b, uint32_t& hi, uint32_t& lo) {
    __nv_bfloat162 h = __floats2bfloat162_rn(a, b);
    float ra = a - __bfloat162float(h.x);
    float rb = b - __bfloat162float(h.y);
    __nv_bfloat162 l = __floats2bfloat162_rn(ra, rb);
    hi = *(uint32_t*)&h; lo = *(uint32_t*)&l;
}

// W row-major [K][64] f32 -> bf16 hi/lo tiles [n][k], 128B SW128 rows
static __device__ __forceinline__ void load_w_tiles(char* smem, const float* W, int K,
                                                    int off_hi0, int off_lo0, int off_hi1, int off_lo1) {
    for (int i = threadIdx.x; i < K * 64; i += THREADS) {
        int k = i >> 6, n = i & 63;
        float v = W[i];
        __nv_bfloat16 h = __float2bfloat16(v);
        float r = v - __bfloat162float(h);
        __nv_bfloat16 l = __float2bfloat16(r);
        int half = k >> 6; int kk = k & 63;
        uint32_t so = swz((uint32_t)(n * 128 + kk * 2));
        *(__nv_bfloat16*)(smem + (half ? off_hi1 : off_hi0) + so) = h;
        *(__nv_bfloat16*)(smem + (half ? off_lo1 : off_lo0) + so) = l;
    }
}

// 3-term hi/lo GEMM: acc += Ahi*Bhi + Alo*Bhi + Ahi*Blo, [128x64]@[64x64]
static __device__ __forceinline__ void gemm_hl(uint32_t sb, uint32_t aHi, uint32_t aLo,
                                               uint32_t bHi, uint32_t bLo,
                                               int wm, int wn, int lane, float acc[2][4][4]) {
    const int arow = lane & 15, acolb = (lane >> 4) * 16;
    const int brow = (lane & 7) + ((lane & 16) ? 8 : 0), bcolb = ((lane >> 3) & 1) * 16;
    #pragma unroll
    for (int s = 0; s < 2; ++s)
        #pragma unroll
        for (int t4 = 0; t4 < 4; ++t4)
            #pragma unroll
            for (int o = 0; o < 4; ++o) acc[s][t4][o] = 0.0f;
    #pragma unroll
    for (int k = 0; k < 4; ++k) {
        uint32_t a[2][2][4], b[2][2][4];
        #pragma unroll
        for (int s = 0; s < 2; ++s) {
            ldsm_x4(a[0][s], sb + aHi + swz((uint32_t)((wm * 32 + s * 16 + arow) * 128 + k * 32 + acolb)));
            ldsm_x4(a[1][s], sb + aLo + swz((uint32_t)((wm * 32 + s * 16 + arow) * 128 + k * 32 + acolb)));
        }
        #pragma unroll
        for (int t = 0; t < 2; ++t) {
            ldsm_x4(b[0][t], sb + bHi + swz((uint32_t)((wn * 32 + t * 16 + brow) * 128 + k * 32 + bcolb)));
            ldsm_x4(b[1][t], sb + bLo + swz((uint32_t)((wn * 32 + t * 16 + brow) * 128 + k * 32 + bcolb)));
        }
        #pragma unroll
        for (int s = 0; s < 2; ++s)
            #pragma unroll
            for (int t4 = 0; t4 < 4; ++t4) {
                mma_bf16(acc[s][t4], a[0][s], &b[0][t4 >> 1][(t4 & 1) * 2]);
                mma_bf16(acc[s][t4], a[1][s], &b[0][t4 >> 1][(t4 & 1) * 2]);
                mma_bf16(acc[s][t4], a[0][s], &b[1][t4 >> 1][(t4 & 1) * 2]);
            }
    }
}

// ---------------- wprep: W2U1b = W2 @ U1_bot, v = b2 @ U1_bot ----------------
__global__ void __launch_bounds__(THREADS)
wprep_kernel(const float* __restrict__ W2, const float* __restrict__ U1,
             const float* __restrict__ b2)
{
    const float* U1b = U1 + 64 * D;
    const int tid = threadIdx.x;
    for (int o = tid; o < D * D; o += THREADS) {
        int k = o >> 6, n = o & 63;
        float s = 0.0f;
        #pragma unroll 8
        for (int j = 0; j < D; ++j)
            s += W2[k * D + j] * U1b[j * D + n];
        g_W2U1b[o] = s;
    }
    if (tid < D) {
        float s = 0.0f;
        #pragma unroll 8
        for (int j = 0; j < D; ++j)
            s += b2[j] * U1b[j * D + tid];
        g_v[tid] = s;
    }
}

// ---------------- precompute: P = x@W1t, Q = x@W1b, R = x@U1t ----------------
__global__ void __launch_bounds__(THREADS)
precompute_kernel(const float* __restrict__ x,
                  const float* __restrict__ W1, const float* __restrict__ U1,
                  int nNodes)
{
    extern __shared__ char smem[];
    const uint32_t sb = smem_u32(smem);
    const int tid = threadIdx.x;
    const int lane = tid & 31, w = tid >> 5;
    const int wm = w >> 1, wn = w & 1;
    const int rA = wm * 32 + (lane >> 2);
    const int cA = wn * 32 + (lane & 3) * 2;

    load_w_tiles(smem, W1, 128, PR_W1T_HI, PR_W1T_LO, PR_W1B_HI, PR_W1B_LO);
    load_w_tiles(smem, U1, 64,  PR_U1T_HI, PR_U1T_LO, PR_U1T_HI, PR_U1T_LO);

    const int nTiles = (nNodes + MTILE - 1) / MTILE;
    for (int t = blockIdx.x; t < nTiles; t += gridDim.x) {
        const int n0 = t * MTILE;
        __syncthreads();
        #pragma unroll 4
        for (int it = 0; it < 8; ++it) {
            int idx = tid + it * THREADS;
            int q = idx & 15;
            int e = idx >> 4;
            int nd = n0 + e; if (nd >= nNodes) nd = nNodes - 1;
            float4 v = ((const float4*)x)[nd * 16 + q];
            uint32_t h01, l01, h23, l23;
            split2(v.x, v.y, h01, l01);
            split2(v.z, v.w, h23, l23);
            uint32_t so = swz((uint32_t)(e * 128 + q * 8));
            *(uint2*)(smem + PR_X_HI + so) = make_uint2(h01, h23);
            *(uint2*)(smem + PR_X_LO + so) = make_uint2(l01, l23);
        }
        __syncthreads();

        float acc[2][4][4];
        #define PR_STORE(OARR) do { \
            _Pragma("unroll") for (int s = 0; s < 2; ++s) \
            _Pragma("unroll") for (int t4 = 0; t4 < 4; ++t4) { \
                int col = cA + t4 * 8, row = rA + s * 16, n1 = n0 + row; \
                if (n1 < nNodes) *(float2*)&OARR[n1 * D + col] = make_float2(acc[s][t4][0], acc[s][t4][1]); \
                if (n1 + 8 < nNodes) *(float2*)&OARR[(n1 + 8) * D + col] = make_float2(acc[s][t4][2], acc[s][t4][3]); \
            } } while (0)

        gemm_hl(sb, PR_X_HI, PR_X_LO, PR_W1T_HI, PR_W1T_LO, wm, wn, lane, acc);
        PR_STORE(g_P);
        gemm_hl(sb, PR_X_HI, PR_X_LO, PR_W1B_HI, PR_W1B_LO, wm, wn, lane, acc);
        PR_STORE(g_Q);
        gemm_hl(sb, PR_X_HI, PR_X_LO, PR_U1T_HI, PR_U1T_LO, wm, wn, lane, acc);
        PR_STORE(g_R);
        #undef PR_STORE
    }
}

// per-block int64/int32 detection (int64 data => odd 32-bit words are 0)
static __device__ __forceinline__ int detect_is64(const int* ei32) {
    int nz = 0;
    if (threadIdx.x < 64) nz = (ei32[2 * threadIdx.x + 1] != 0);
    return !__syncthreads_or(nz);
}

// ---------------- hist: cnt[dst]++ ----------------
__global__ void __launch_bounds__(THREADS)
hist_kernel(const void* __restrict__ ei, int nEdges, int nNodes)
{
    const int* ei32 = (const int*)ei;
    const int is64 = detect_is64(ei32);
    const long long* ei64 = (const long long*)ei;
    int i0 = blockIdx.x * THREADS + threadIdx.x;
    int stride = gridDim.x * THREADS;
    for (int e = i0; e < nEdges; e += stride) {
        int dn = is64 ? (int)ei64[nEdges + e] : ei32[nEdges + e];
        dn = min(max(dn, 0), nNodes - 1);
        atomicAdd(&g_cnt[dn], 1);
    }
}

// ---------------- scan1: per-256-chunk exclusive scan + chunk totals ----------------
__global__ void __launch_bounds__(256)
scan1_kernel(int nNodes)
{
    __shared__ int sh[256];
    int t = threadIdx.x;
    int i = blockIdx.x * 256 + t;
    int v = (i < nNodes) ? g_cnt[i] : 0;
    sh[t] = v;
    __syncthreads();
    #pragma unroll
    for (int d = 1; d < 256; d <<= 1) {
        int add = (t >= d) ? sh[t - d] : 0;
        __syncthreads();
        sh[t] += add;
        __syncthreads();
    }
    if (i < nNodes) g_start[i] = sh[t] - v;       // exclusive within chunk
    if (t == 255) g_btot[blockIdx.x] = sh[255];
}

// ---------------- scan2: exclusive scan of chunk totals (1 block) ----------------
__global__ void __launch_bounds__(256)
scan2_kernel(int nChunks)
{
    __shared__ int sh[256];
    int t = threadIdx.x;
    int v = (t < nChunks) ? g_btot[t] : 0;
    sh[t] = v;
    __syncthreads();
    #pragma unroll
    for (int d = 1; d < 256; d <<= 1) {
        int add = (t >= d) ? sh[t - d] : 0;
        __syncthreads();
        sh[t] += add;
        __syncthreads();
    }
    g_boff[t] = sh[t] - v;
}

// ---------------- scan3: add chunk offsets; init cursors ----------------
__global__ void __launch_bounds__(256)
scan3_kernel(int nNodes)
{
    int i = blockIdx.x * 256 + threadIdx.x;
    if (i < nNodes) {
        int s = g_start[i] + g_boff[blockIdx.x];
        g_start[i] = s;
        g_cur[i] = s;
    }
}

// ---------------- fill: elist[pos[dst]++] = src ----------------
__global__ void __launch_bounds__(THREADS)
fill_kernel(const void* __restrict__ ei, int nEdges, int nNodes)
{
    const int* ei32 = (const int*)ei;
    const int is64 = detect_is64(ei32);
    const long long* ei64 = (const long long*)ei;
    int i0 = blockIdx.x * THREADS + threadIdx.x;
    int stride = gridDim.x * THREADS;
    for (int e = i0; e < nEdges; e += stride) {
        int sn = is64 ? (int)ei64[e] : ei32[e];
        int dn = is64 ? (int)ei64[nEdges + e] : ei32[nEdges + e];
        sn = min(max(sn, 0), nNodes - 1);
        dn = min(max(dn, 0), nNodes - 1);
        int pos = atomicAdd(&g_cur[dn], 1);
        g_elist[pos] = sn;
    }
}

// ---------------- aggr: S[n] = sum_{e in bin(n)} relu(P[n]+Q[src_e]+b1) ----------------
__global__ void __launch_bounds__(THREADS)
aggr_kernel(const float* __restrict__ b1, int nNodes)
{
    const int tid = threadIdx.x;
    const int lane = tid & 31;
    const int q = lane & 15;
    const unsigned gmask = 0xFFFFu << (lane & 16);
    const float4 b1q = ((const float4*)b1)[q];
    int grp0 = (blockIdx.x * THREADS + tid) >> 4;
    int ngrp = (gridDim.x * THREADS) >> 4;

    for (int n = grp0; n < nNodes; n += ngrp) {
        int s0 = g_start[n];
        int cnt = g_cnt[n];
        int end = s0 + cnt;
        float4 p = ((const float4*)g_P)[n * 16 + q];
        float ax = 0.f, ay = 0.f, az = 0.f, aw = 0.f;
        for (int j = s0; j < end; j += 16) {
            int myv = (j + q < end) ? g_elist[j + q] : 0;
            int lim = min(16, end - j);
            #pragma unroll 4
            for (int t = 0; t < lim; ++t) {
                int src = __shfl_sync(gmask, myv, t, 16);
                float4 qq = ((const float4*)g_Q)[src * 16 + q];
                ax += fmaxf(p.x + qq.x + b1q.x, 0.0f);
                ay += fmaxf(p.y + qq.y + b1q.y, 0.0f);
                az += fmaxf(p.z + qq.z + b1q.z, 0.0f);
                aw += fmaxf(p.w + qq.w + b1q.w, 0.0f);
            }
        }
        ((float4*)g_aggr)[n * 16 + q] = make_float4(ax, ay, az, aw);
    }
}

// ---------------- node kernel: out = relu(R + S@W2U1b + deg*v + ub1)@U2 + ub2 ----------------
__global__ void __launch_bounds__(THREADS, 2)
node_kernel(const float* __restrict__ ub1, const float* __restrict__ ub2,
            const float* __restrict__ U2,
            float* __restrict__ out, int nNodes)
{
    extern __shared__ char smem[];
    const uint32_t sb = smem_u32(smem);
    const int tid = threadIdx.x;
    const int lane = tid & 31, w = tid >> 5;
    const int wm = w >> 1, wn = w & 1;
    const int rA = wm * 32 + (lane >> 2);
    const int cA = wn * 32 + (lane & 3) * 2;
    float* sB1 = (float*)(smem + ND_B1);
    float* sB2 = (float*)(smem + ND_B2);
    float* sV  = (float*)(smem + ND_V);

    load_w_tiles(smem, g_W2U1b, 64, ND_WF_HI, ND_WF_LO, ND_WF_HI, ND_WF_LO);
    load_w_tiles(smem, U2, 64, ND_U2_HI, ND_U2_LO, ND_U2_HI, ND_U2_LO);
    if (tid < 64) { sB1[tid] = ub1[tid]; sB2[tid] = ub2[tid]; sV[tid] = g_v[tid]; }

    const int nTiles = (nNodes + MTILE - 1) / MTILE;
    for (int t = blockIdx.x; t < nTiles; t += gridDim.x) {
        const int n0 = t * MTILE;
        __syncthreads();

        // gather S -> A hi/lo (coalesced)
        #pragma unroll 4
        for (int it = 0; it < 8; ++it) {
            int idx = tid + it * THREADS;
            int q = idx & 15;
            int e = idx >> 4;
            int nd = n0 + e; if (nd >= nNodes) nd = nNodes - 1;
            float4 v = ((const float4*)g_aggr)[nd * 16 + q];
            uint32_t h01, l01, h23, l23;
            split2(v.x, v.y, h01, l01);
            split2(v.z, v.w, h23, l23);
            uint32_t so = swz((uint32_t)(e * 128 + q * 8));
            *(uint2*)(smem + ND_A_HI + so) = make_uint2(h01, h23);
            *(uint2*)(smem + ND_A_LO + so) = make_uint2(l01, l23);
        }
        __syncthreads();

        float acc[2][4][4];
        gemm_hl(sb, ND_A_HI, ND_A_LO, ND_WF_HI, ND_WF_LO, wm, wn, lane, acc);
        __syncthreads();   // all warps done reading A before overlay write

        // h = relu(acc + R + deg*v + ub1) -> H (overlays A)
        #pragma unroll
        for (int s = 0; s < 2; ++s) {
            int row = rA + s * 16;
            int n1 = n0 + row;
            float dg0 = (n1 < nNodes) ? (float)g_cnt[n1] : 0.0f;
            float dg1 = (n1 + 8 < nNodes) ? (float)g_cnt[n1 + 8] : 0.0f;
            #pragma unroll
            for (int t4 = 0; t4 < 4; ++t4) {
                int col = cA + t4 * 8;
                float2 ra = (n1 < nNodes) ? *(const float2*)&g_R[n1 * D + col] : make_float2(0.f, 0.f);
                float2 rb = (n1 + 8 < nNodes) ? *(const float2*)&g_R[(n1 + 8) * D + col] : make_float2(0.f, 0.f);
                float v0 = fmaxf(acc[s][t4][0] + ra.x + dg0 * sV[col]     + sB1[col],     0.0f);
                float v1 = fmaxf(acc[s][t4][1] + ra.y + dg0 * sV[col + 1] + sB1[col + 1], 0.0f);
                uint32_t hi, lo; split2(v0, v1, hi, lo);
                uint32_t so = swz((uint32_t)(row * 128 + col * 2));
                *(uint32_t*)(smem + ND_A_HI + so) = hi;
                *(uint32_t*)(smem + ND_A_LO + so) = lo;
                float v2 = fmaxf(acc[s][t4][2] + rb.x + dg1 * sV[col]     + sB1[col],     0.0f);
                float v3 = fmaxf(acc[s][t4][3] + rb.y + dg1 * sV[col + 1] + sB1[col + 1], 0.0f);
                split2(v2, v3, hi, lo);
                so = swz((uint32_t)((row + 8) * 128 + col * 2));
                *(uint32_t*)(smem + ND_A_HI + so) = hi;
                *(uint32_t*)(smem + ND_A_LO + so) = lo;
            }
        }
        __syncthreads();

        float acc2[2][4][4];
        gemm_hl(sb, ND_A_HI, ND_A_LO, ND_U2_HI, ND_U2_LO, wm, wn, lane, acc2);

        #pragma unroll
        for (int s = 0; s < 2; ++s)
            #pragma unroll
            for (int t4 = 0; t4 < 4; ++t4) {
                int col = cA + t4 * 8;
                int row = rA + s * 16;
                int n1 = n0 + row;
                if (n1 < nNodes)
                    *(float2*)&out[n1 * D + col] =
                        make_float2(acc2[s][t4][0] + sB2[col], acc2[s][t4][1] + sB2[col + 1]);
                if (n1 + 8 < nNodes)
                    *(float2*)&out[(n1 + 8) * D + col] =
                        make_float2(acc2[s][t4][2] + sB2[col], acc2[s][t4][3] + sB2[col + 1]);
            }
    }
}

extern "C" void kernel_launch(void* const* d_in, const int* in_sizes, int n_in,
                              void* d_out, int out_size)
{
    const float* x   = (const float*)d_in[0];
    const void*  ei  = d_in[1];
    const float* W1  = (const float*)d_in[2];
    const float* b1  = (const float*)d_in[3];
    const float* W2  = (const float*)d_in[4];
    const float* b2  = (const float*)d_in[5];
    const float* U1  = (const float*)d_in[6];
    const float* ub1 = (const float*)d_in[7];
    const float* U2  = (const float*)d_in[8];
    const float* ub2 = (const float*)d_in[9];
    float* out = (float*)d_out;

    const int nEdges = in_sizes[1] / 2;
    const int nNodes = in_sizes[0] / D;

    void* cnt_ptr = nullptr;
    cudaGetSymbolAddress(&cnt_ptr, g_cnt);

    cudaFuncSetAttribute(precompute_kernel, cudaFuncAttributeMaxDynamicSharedMemorySize, PR_SMEM);
    cudaFuncSetAttribute(node_kernel, cudaFuncAttributeMaxDynamicSharedMemorySize, ND_SMEM);

    const int nodeTiles = (nNodes + MTILE - 1) / MTILE;
    const int nChunks = (nNodes + 255) / 256;
    const int aggrBlocks = (nNodes * 16 + THREADS - 1) / THREADS;

    cudaMemsetAsync(cnt_ptr, 0, (size_t)nNodes * sizeof(int), 0);
    wprep_kernel<<<1, THREADS>>>(W2, U1, b2);
    precompute_kernel<<<nodeTiles < 296 ? nodeTiles : 296, THREADS, PR_SMEM>>>(x, W1, U1, nNodes);
    hist_kernel<<<592, THREADS>>>(ei, nEdges, nNodes);
    scan1_kernel<<<nChunks, 256>>>(nNodes);
    scan2_kernel<<<1, 256>>>(nChunks);
    scan3_kernel<<<nChunks, 256>>>(nNodes);
    fill_kernel<<<592, THREADS>>>(ei, nEdges, nNodes);
    aggr_kernel<<<aggrBlocks, THREADS>>>(b1, nNodes);
    node_kernel<<<nodeTiles < 296 ? nodeTiles : 296, THREADS, ND_SMEM>>>(ub1, ub2, U2, out, nNodes);
}